// round 14
// baseline (speedup 1.0000x reference)
#include <cuda_runtime.h>
#include <cuda_fp16.h>
#include <stdint.h>

#define CROSS   3
#define THREADS 128
#define NPASS   (CROSS * 17)

// ---------------- fragment-layout weight blob ----------------
// u32 index: ((((g*4 + cg)*16 + s*4 + t)*32) + lane)*4 + q
// value: halves W_g[n][k], W_g[n][k+1] with
//   n = cg*64 + t*16 + (q&1)*8 + (lane>>2)
//   k = s*16 + (q>>1)*8 + 2*(lane&3)
__device__ __align__(16) uint32_t gWF[NPASS * 8192];
// gate plane image: [8 n][512 k] fp16, rowstride 1024B
__device__ __align__(16) __half gGB[4096];

__global__ void prep_kernel(const float* __restrict__ Vs,
                            const float* __restrict__ Cs,
                            const float* __restrict__ Us,
                            const float* __restrict__ gw) {
    int idx = blockIdx.x * 256 + threadIdx.x;
    const int NF = NPASS * 8192;
    if (idx < NF) {
        int q    = idx & 3;
        int lane = (idx >> 2) & 31;
        int t    = (idx >> 7) & 3;
        int s    = (idx >> 9) & 3;
        int cg   = (idx >> 11) & 3;
        int g    = idx >> 13;
        int n = cg * 64 + t * 16 + (q & 1) * 8 + (lane >> 2);
        int k = s * 16 + ((q >> 1) & 1) * 8 + 2 * (lane & 3);
        int L = g / 17, p = g - L * 17;
        float w0, w1;
        if (p < 8) {
            const float* src = Vs + (size_t)(L * 256 + n) * 512 + p * 64 + k;
            w0 = src[0]; w1 = src[1];
        } else if (p == 8) {
            const float* src = Cs + (size_t)L * 16384 + n * 64 + k;
            w0 = src[0]; w1 = src[1];
        } else {
            int qq = p - 9, h = qq >> 2, c = qq & 3;
            const float* src = Us + ((size_t)(L * 4 + c) * 512 + h * 256 + n) * 64 + k;
            w0 = src[0]; w1 = src[1];
        }
        __half h0 = __float2half_rn(w0), h1 = __float2half_rn(w1);
        gWF[idx] = (uint32_t)*(unsigned short*)&h0 | ((uint32_t)*(unsigned short*)&h1 << 16);
        return;
    }
    idx -= NF;
    if (idx < 4096) {
        int n = idx >> 9, k = idx & 511;
        float w = (n < 4) ? gw[k * 4 + n] : 0.f;
        gGB[(n * 1024 + ((2 * k) ^ ((n & 7) << 4))) >> 1] = __float2half_rn(w);
    }
}

// ---------------- warp-level primitives ----------------
__device__ __forceinline__ uint32_t s2u(const void* p) {
    uint32_t a;
    asm("{ .reg .u64 t; cvta.to.shared.u64 t, %1; cvt.u32.u64 %0, t; }" : "=r"(a) : "l"(p));
    return a;
}
__device__ __forceinline__ void ldsm4(uint32_t r[4], uint32_t addr) {
    asm volatile("ldmatrix.sync.aligned.m8n8.x4.shared.b16 {%0,%1,%2,%3}, [%4];"
                 : "=r"(r[0]), "=r"(r[1]), "=r"(r[2]), "=r"(r[3]) : "r"(addr));
}
__device__ __forceinline__ void ldsm2(uint32_t r[2], uint32_t addr) {
    asm volatile("ldmatrix.sync.aligned.m8n8.x2.shared.b16 {%0,%1}, [%2];"
                 : "=r"(r[0]), "=r"(r[1]) : "r"(addr));
}
__device__ __forceinline__ void mma_f16(float d[4], const uint32_t a[4], const uint32_t b0, const uint32_t b1) {
    asm volatile("mma.sync.aligned.m16n8k16.row.col.f32.f16.f16.f32 "
                 "{%0,%1,%2,%3}, {%4,%5,%6,%7}, {%8,%9}, {%0,%1,%2,%3};"
                 : "+f"(d[0]), "+f"(d[1]), "+f"(d[2]), "+f"(d[3])
                 : "r"(a[0]), "r"(a[1]), "r"(a[2]), "r"(a[3]), "r"(b0), "r"(b1));
}
__device__ __forceinline__ float fast_tanh(float x) {
    asm("tanh.approx.f32 %0, %0;" : "+f"(x));
    return x;
}
__device__ __forceinline__ uint32_t packh(float a, float b) {
    __half2 p = __floats2half2_rn(a, b);
    return *(uint32_t*)&p;
}
__device__ __forceinline__ void split2h(float a, float b, uint32_t& hw, uint32_t& mw) {
    __half h0 = __float2half_rn(a), h1 = __float2half_rn(b);
    __half m0 = __float2half_rn(a - __half2float(h0));
    __half m1 = __float2half_rn(b - __half2float(h1));
    hw = (uint32_t)*(unsigned short*)&h0 | ((uint32_t)*(unsigned short*)&h1 << 16);
    mw = (uint32_t)*(unsigned short*)&m0 | ((uint32_t)*(unsigned short*)&m1 << 16);
}
__device__ __forceinline__ float hlo(uint32_t w) {
    unsigned short s = (unsigned short)(w & 0xFFFF);
    return __half2float(*(__half*)&s);
}
__device__ __forceinline__ float hhi(uint32_t w) {
    unsigned short s = (unsigned short)(w >> 16);
    return __half2float(*(__half*)&s);
}
__device__ __forceinline__ void copy16(char* dst, const char* src, int bytes, int tid) {
    const float4* s = (const float4*)src;
    float4* d = (float4*)dst;
    for (int i = tid; i < bytes / 16; i += THREADS) d[i] = s[i];
}

// warp tile = 32 rows x 64 cols. acc[rowfrag 2][n16 4][n8 2][4].
// A via ldsm from smem plane; B via direct LDG.128 of fragment blob.
__device__ __forceinline__ void mma_ldg(
    uint32_t aB0, uint32_t aB1,
    const uint4* __restrict__ wp,        // gWF_u4 + g*2048 + cg*512 + lane
    const uint32_t kx[4],
    float (&acc)[2][4][2][4])
{
    uint4 b[16];
    #pragma unroll
    for (int i = 0; i < 16; ++i) b[i] = __ldg(wp + i * 32);
    #pragma unroll
    for (int s = 0; s < 4; ++s) {
        uint32_t a0[4], a1[4];
        ldsm4(a0, aB0 + kx[s]);
        ldsm4(a1, aB1 + kx[s]);
        #pragma unroll
        for (int t = 0; t < 4; ++t) {
            const uint4 bb = b[s * 4 + t];
            mma_f16(acc[0][t][0], a0, bb.x, bb.z);
            mma_f16(acc[0][t][1], a0, bb.y, bb.w);
            mma_f16(acc[1][t][0], a1, bb.x, bb.z);
            mma_f16(acc[1][t][1], a1, bb.y, bb.w);
        }
    }
}

#define ZEROACC                                       \
    _Pragma("unroll") for (int zi = 0; zi < 2; ++zi)  \
    _Pragma("unroll") for (int zj = 0; zj < 4; ++zj)  \
    _Pragma("unroll") for (int zk = 0; zk < 2; ++zk)  \
    _Pragma("unroll") for (int zl = 0; zl < 4; ++zl) acc[zi][zj][zk][zl] = 0.f;

// smem byte offsets (32-row CTA)
#define O_XH 0          // x_l hi plane  [32][512] fp16 (32KB)
#define O_XM 32768      // x_l mid plane (32KB)
#define O_V  65536      // v / c' plane  [32][256] fp16 (16KB)
#define O_GT 81920      // gate plane (8KB, staged once)
#define O_G  90112      // sG [32][4] f32
#define O_GS 90624      // sGS [32] f32
#define SMEM_BYTES 90752

__global__ void __launch_bounds__(THREADS, 2)
dcn_kernel(const float* __restrict__ x,
           const float* __restrict__ bias,
           float* __restrict__ out)
{
    extern __shared__ char sm[];
    const uint32_t sb = s2u(sm);
    const int tid = threadIdx.x;
    const int w = tid >> 5, lane = tid & 31;
    const int row0 = blockIdx.x * 32;
    const int cg = w;                      // 0..3 (64-col groups)
    const int nbase = cg * 64;             // expert for this warp's columns = cg

    // ---- hoisted ldsm addressing (per-thread constants; A-side only) ----
    const uint32_t lr = (uint32_t)(lane & 15);
    const uint32_t lk = (uint32_t)((lane >> 4) << 4);
    const uint32_t csw = (uint32_t)((lane & 7) << 4);
    uint32_t kx[4];
    #pragma unroll
    for (int s = 0; s < 4; ++s) kx[s] = ((uint32_t)(s * 32) + lk) ^ csw;
    const uint32_t aX0 = sb + O_XH + (0  + lr) * 1024;
    const uint32_t aX1 = sb + O_XH + (16 + lr) * 1024;
    const uint32_t aV0 = sb + O_V  + (0  + lr) * 512;
    const uint32_t aV1 = sb + O_V  + (16 + lr) * 512;

    // per-thread fragment pointer base: + g*2048 (uint4) per pass
    const uint4* __restrict__ wf0 = (const uint4*)gWF + (uint32_t)(cg * 512 + lane);

    float* sG  = (float*)(sm + O_G);
    float* sGS = (float*)(sm + O_GS);

    // ---- init: x -> fp16 hi/mid planes; gate plane staged once ----
    copy16(sm + O_GT, (const char*)gGB, 8192, tid);
    for (int i = tid; i < 32 * 256; i += THREADS) {
        int r = i >> 8, kp = i & 255;
        float2 v = *(const float2*)(x + (size_t)(row0 + r) * 512 + 2 * kp);
        uint32_t hw, mw;
        split2h(v.x, v.y, hw, mw);
        uint32_t off = (uint32_t)r * 1024 + (((uint32_t)(4 * kp)) ^ (((uint32_t)r & 7) << 4));
        *(uint32_t*)(sm + O_XH + off) = hw;
        *(uint32_t*)(sm + O_XM + off) = mw;
    }
    __syncthreads();

    float acc[2][4][2][4];

    #pragma unroll 1
    for (int L = 0; L < CROSS; ++L) {
        const int g0 = L * 17;
        const uint4* __restrict__ wL = wf0 + (uint32_t)g0 * 2048;

        // ---- gate (warps 0-1): reads XH + static gate plane ----
        if (w < 2) {
            float ga[4] = {0.f, 0.f, 0.f, 0.f};
            #pragma unroll 4
            for (int s = 0; s < 32; ++s) {
                uint32_t kb = s * 32;
                uint32_t r = (uint32_t)(w * 16) + lr;
                uint32_t ah[4];
                ldsm4(ah, sb + O_XH + r * 1024 + ((kb + lk) ^ ((r & 7) << 4)));
                uint32_t bn = lane & 7;
                uint32_t bk = kb + (((lane >> 3) & 1) << 4);
                uint32_t bh[2];
                ldsm2(bh, sb + O_GT + bn * 1024 + (bk ^ ((bn & 7) << 4)));
                mma_f16(ga, ah, bh[0], bh[1]);
            }
            int c0 = (lane & 3) * 2;
            if (c0 < 4) {
                int r1 = w * 16 + (lane >> 2);
                sG[r1 * 4 + c0] = ga[0];       sG[r1 * 4 + c0 + 1] = ga[1];
                sG[(r1 + 8) * 4 + c0] = ga[2]; sG[(r1 + 8) * 4 + c0 + 1] = ga[3];
            }
        }

        // ---- V: v = tanh(Vs @ x_l), K=512, 8 barrier-free passes ----
        ZEROACC;
        #pragma unroll
        for (int c = 0; c < 8; ++c)
            mma_ldg(aX0 + c * 128, aX1 + c * 128, wL + c * 2048, kx, acc);
        // V epilogue -> V plane
        #pragma unroll
        for (int rf = 0; rf < 2; ++rf)
        #pragma unroll
        for (int t = 0; t < 4; ++t)
        #pragma unroll
        for (int nb = 0; nb < 2; ++nb) {
            float* d = acc[rf][t][nb];
            int n = nbase + t * 16 + nb * 8 + (lane & 3) * 2;
            #pragma unroll
            for (int rr = 0; rr < 2; ++rr) {
                int r = rf * 16 + (lane >> 2) + rr * 8;
                uint32_t off = (uint32_t)r * 512 + (((uint32_t)(2 * n)) ^ (((uint32_t)r & 7) << 4));
                *(uint32_t*)(sm + O_V + off) =
                    packh(fast_tanh(d[rr * 2 + 0]), fast_tanh(d[rr * 2 + 1]));
            }
        }
        __syncthreads();   // V plane + sG visible to all

        if (tid < 32)
            sGS[tid] = sG[tid * 4] + sG[tid * 4 + 1] + sG[tid * 4 + 2] + sG[tid * 4 + 3];

        // ---- C: block diagonal, one pass ----
        // warp cg's columns (cg*64..cg*64+63) all belong to expert cg:
        // A k-window = expert's 64 v-columns = byte offset cg*128.
        ZEROACC;
        mma_ldg(aV0 + (uint32_t)cg * 128, aV1 + (uint32_t)cg * 128,
                wL + 8 * 2048, kx, acc);
        __syncthreads();   // all C-mma reads of V done before overwrite
        #pragma unroll
        for (int rf = 0; rf < 2; ++rf)
        #pragma unroll
        for (int t = 0; t < 4; ++t)
        #pragma unroll
        for (int nb = 0; nb < 2; ++nb) {
            float* d = acc[rf][t][nb];
            int n = nbase + t * 16 + nb * 8 + (lane & 3) * 2;
            #pragma unroll
            for (int rr = 0; rr < 2; ++rr) {
                int r = rf * 16 + (lane >> 2) + rr * 8;
                float g = sG[r * 4 + cg];
                uint32_t off = (uint32_t)r * 512 + (((uint32_t)(2 * n)) ^ (((uint32_t)r & 7) << 4));
                *(uint32_t*)(sm + O_V + off) =
                    packh(g * fast_tanh(d[rr * 2 + 0]), g * fast_tanh(d[rr * 2 + 1]));
            }
        }
        __syncthreads();   // c' visible

        // ---- U: two 256-d halves x 4 expert chunks; fused combine ----
        #pragma unroll 1
        for (int h = 0; h < 2; ++h) {
            ZEROACC;
            #pragma unroll
            for (int c = 0; c < 4; ++c)
                mma_ldg(aV0 + c * 128, aV1 + c * 128,
                        wL + (9 + h * 4 + c) * 2048, kx, acc);
            // epilogue: out = x0*(u + bias*gs) + x_l
            #pragma unroll
            for (int rf = 0; rf < 2; ++rf)
            #pragma unroll
            for (int t = 0; t < 4; ++t)
            #pragma unroll
            for (int nb = 0; nb < 2; ++nb) {
                float* d = acc[rf][t][nb];
                int dc = h * 256 + nbase + t * 16 + nb * 8 + (lane & 3) * 2;
                float2 bv = *(const float2*)(bias + L * 512 + dc);
                #pragma unroll
                for (int rr = 0; rr < 2; ++rr) {
                    int r = rf * 16 + (lane >> 2) + rr * 8;
                    float gs = sGS[r];
                    float2 x0 = *(const float2*)(x + (size_t)(row0 + r) * 512 + dc);
                    uint32_t off = (uint32_t)r * 1024 + (((uint32_t)(2 * dc)) ^ (((uint32_t)r & 7) << 4));
                    uint32_t xh = *(uint32_t*)(sm + O_XH + off);
                    uint32_t xm = *(uint32_t*)(sm + O_XM + off);
                    float xl0 = hlo(xh) + hlo(xm);
                    float xl1 = hhi(xh) + hhi(xm);
                    float o0 = x0.x * (d[rr * 2 + 0] + bv.x * gs) + xl0;
                    float o1 = x0.y * (d[rr * 2 + 1] + bv.y * gs) + xl1;
                    if (L == CROSS - 1) {
                        *(float2*)(out + (size_t)(row0 + r) * 512 + dc) = make_float2(o0, o1);
                    } else {
                        uint32_t hw, mw;
                        split2h(o0, o1, hw, mw);
                        *(uint32_t*)(sm + O_XH + off) = hw;
                        *(uint32_t*)(sm + O_XM + off) = mw;
                    }
                }
            }
        }
        __syncthreads();   // XH/XM updated before next layer's reads
    }
}

extern "C" void kernel_launch(void* const* d_in, const int* in_sizes, int n_in,
                              void* d_out, int out_size) {
    const float* x    = (const float*)d_in[0];
    const float* Vs   = (const float*)d_in[1];
    const float* Cs   = (const float*)d_in[2];
    const float* Us   = (const float*)d_in[3];
    const float* bias = (const float*)d_in[4];
    const float* gate = (const float*)d_in[5];
    float* out = (float*)d_out;

    const int total = NPASS * 8192 + 4096;
    prep_kernel<<<(total + 255) / 256, 256>>>(Vs, Cs, Us, gate);

    int rows = in_sizes[0] / 512;
    int grid = rows / 32;

    cudaFuncSetAttribute(dcn_kernel, cudaFuncAttributeMaxDynamicSharedMemorySize, SMEM_BYTES);
    dcn_kernel<<<grid, THREADS, SMEM_BYTES>>>(x, bias, out);
}

// round 15
// speedup vs baseline: 1.1200x; 1.1200x over previous
#include <cuda_runtime.h>
#include <cuda_fp16.h>
#include <stdint.h>

#define CROSS   3
#define THREADS 256
#define NPASS   (CROSS * 17)

// ---------------- fragment-layout weight blob (64-col groups) ----------------
// u32 index: ((((g*4 + cg)*16 + s*4 + t)*32) + lane)*4 + q
// value: halves W_g[n][k], W_g[n][k+1] with
//   n = cg*64 + t*16 + (q&1)*8 + (lane>>2)
//   k = s*16 + (q>>1)*8 + 2*(lane&3)
__device__ __align__(16) uint32_t gWF[NPASS * 8192];
// gate plane image: [8 n][512 k] fp16, rowstride 1024B
__device__ __align__(16) __half gGB[4096];
// x_l mid plane scratch: one u32 (half2) per (row, dc-pair): [32768][256]
__device__ __align__(16) uint32_t gXM[32768u * 256u];

__global__ void prep_kernel(const float* __restrict__ Vs,
                            const float* __restrict__ Cs,
                            const float* __restrict__ Us,
                            const float* __restrict__ gw) {
    int idx = blockIdx.x * 256 + threadIdx.x;
    const int NF = NPASS * 8192;
    if (idx < NF) {
        int q    = idx & 3;
        int lane = (idx >> 2) & 31;
        int t    = (idx >> 7) & 3;
        int s    = (idx >> 9) & 3;
        int cg   = (idx >> 11) & 3;
        int g    = idx >> 13;
        int n = cg * 64 + t * 16 + (q & 1) * 8 + (lane >> 2);
        int k = s * 16 + ((q >> 1) & 1) * 8 + 2 * (lane & 3);
        int L = g / 17, p = g - L * 17;
        float w0, w1;
        if (p < 8) {
            const float* src = Vs + (size_t)(L * 256 + n) * 512 + p * 64 + k;
            w0 = src[0]; w1 = src[1];
        } else if (p == 8) {
            const float* src = Cs + (size_t)L * 16384 + n * 64 + k;
            w0 = src[0]; w1 = src[1];
        } else {
            int qq = p - 9, h = qq >> 2, c = qq & 3;
            const float* src = Us + ((size_t)(L * 4 + c) * 512 + h * 256 + n) * 64 + k;
            w0 = src[0]; w1 = src[1];
        }
        __half h0 = __float2half_rn(w0), h1 = __float2half_rn(w1);
        gWF[idx] = (uint32_t)*(unsigned short*)&h0 | ((uint32_t)*(unsigned short*)&h1 << 16);
        return;
    }
    idx -= NF;
    if (idx < 4096) {
        int n = idx >> 9, k = idx & 511;
        float w = (n < 4) ? gw[k * 4 + n] : 0.f;
        gGB[(n * 1024 + ((2 * k) ^ ((n & 7) << 4))) >> 1] = __float2half_rn(w);
    }
}

// ---------------- warp-level primitives ----------------
__device__ __forceinline__ uint32_t s2u(const void* p) {
    uint32_t a;
    asm("{ .reg .u64 t; cvta.to.shared.u64 t, %1; cvt.u32.u64 %0, t; }" : "=r"(a) : "l"(p));
    return a;
}
__device__ __forceinline__ void ldsm4(uint32_t r[4], uint32_t addr) {
    asm volatile("ldmatrix.sync.aligned.m8n8.x4.shared.b16 {%0,%1,%2,%3}, [%4];"
                 : "=r"(r[0]), "=r"(r[1]), "=r"(r[2]), "=r"(r[3]) : "r"(addr));
}
__device__ __forceinline__ void ldsm2(uint32_t r[2], uint32_t addr) {
    asm volatile("ldmatrix.sync.aligned.m8n8.x2.shared.b16 {%0,%1}, [%2];"
                 : "=r"(r[0]), "=r"(r[1]) : "r"(addr));
}
__device__ __forceinline__ void mma_f16(float d[4], const uint32_t a[4], const uint32_t b0, const uint32_t b1) {
    asm volatile("mma.sync.aligned.m16n8k16.row.col.f32.f16.f16.f32 "
                 "{%0,%1,%2,%3}, {%4,%5,%6,%7}, {%8,%9}, {%0,%1,%2,%3};"
                 : "+f"(d[0]), "+f"(d[1]), "+f"(d[2]), "+f"(d[3])
                 : "r"(a[0]), "r"(a[1]), "r"(a[2]), "r"(a[3]), "r"(b0), "r"(b1));
}
__device__ __forceinline__ float fast_tanh(float x) {
    asm("tanh.approx.f32 %0, %0;" : "+f"(x));
    return x;
}
__device__ __forceinline__ uint32_t packh(float a, float b) {
    __half2 p = __floats2half2_rn(a, b);
    return *(uint32_t*)&p;
}
__device__ __forceinline__ void split2h(float a, float b, uint32_t& hw, uint32_t& mw) {
    __half h0 = __float2half_rn(a), h1 = __float2half_rn(b);
    __half m0 = __float2half_rn(a - __half2float(h0));
    __half m1 = __float2half_rn(b - __half2float(h1));
    hw = (uint32_t)*(unsigned short*)&h0 | ((uint32_t)*(unsigned short*)&h1 << 16);
    mw = (uint32_t)*(unsigned short*)&m0 | ((uint32_t)*(unsigned short*)&m1 << 16);
}
__device__ __forceinline__ float hlo(uint32_t w) {
    unsigned short s = (unsigned short)(w & 0xFFFF);
    return __half2float(*(__half*)&s);
}
__device__ __forceinline__ float hhi(uint32_t w) {
    unsigned short s = (unsigned short)(w >> 16);
    return __half2float(*(__half*)&s);
}
__device__ __forceinline__ void copy16(char* dst, const char* src, int bytes, int tid) {
    const float4* s = (const float4*)src;
    float4* d = (float4*)dst;
    for (int i = tid; i < bytes / 16; i += THREADS) d[i] = s[i];
}

// warp tile = 32 rows x 64 cols. acc[rowfrag 2][n16 4][n8 2][4].
// A via ldsm from smem plane; B via direct LDG.128 of fragment blob,
// staged in TWO rounds of 8 uint4 to bound register pressure.
__device__ __forceinline__ void mma_ldg(
    uint32_t aB0, uint32_t aB1,
    const uint4* __restrict__ wp,        // gWF_u4 + g*2048 + cg*512 + lane
    const uint32_t kx[4],
    float (&acc)[2][4][2][4])
{
    #pragma unroll
    for (int hf = 0; hf < 2; ++hf) {
        uint4 b[8];
        #pragma unroll
        for (int i = 0; i < 8; ++i) b[i] = __ldg(wp + (hf * 8 + i) * 32);
        #pragma unroll
        for (int si = 0; si < 2; ++si) {
            const int s = hf * 2 + si;
            uint32_t a0[4], a1[4];
            ldsm4(a0, aB0 + kx[s]);
            ldsm4(a1, aB1 + kx[s]);
            #pragma unroll
            for (int t = 0; t < 4; ++t) {
                const uint4 bb = b[si * 4 + t];
                mma_f16(acc[0][t][0], a0, bb.x, bb.z);
                mma_f16(acc[0][t][1], a0, bb.y, bb.w);
                mma_f16(acc[1][t][0], a1, bb.x, bb.z);
                mma_f16(acc[1][t][1], a1, bb.y, bb.w);
            }
        }
    }
}

#define ZEROACC                                       \
    _Pragma("unroll") for (int zi = 0; zi < 2; ++zi)  \
    _Pragma("unroll") for (int zj = 0; zj < 4; ++zj)  \
    _Pragma("unroll") for (int zk = 0; zk < 2; ++zk)  \
    _Pragma("unroll") for (int zl = 0; zl < 4; ++zl) acc[zi][zj][zk][zl] = 0.f;

// smem byte offsets (64-row CTA; XM lives in global scratch)
#define O_XH 0          // x_l hi plane  [64][512] fp16 (64KB)
#define O_V  65536      // v / c' plane  [64][256] fp16 (32KB)
#define O_GT 98304      // gate plane (8KB, staged once)
#define O_G  106496     // sG [64][4] f32 (1KB)
#define O_GS 107520     // sGS [64] f32 (256B)
#define SMEM_BYTES 107776

__global__ void __launch_bounds__(THREADS, 2)
dcn_kernel(const float* __restrict__ x,
           const float* __restrict__ bias,
           float* __restrict__ out)
{
    extern __shared__ char sm[];
    const uint32_t sb = s2u(sm);
    const int tid = threadIdx.x;
    const int w = tid >> 5, lane = tid & 31;
    const int row0 = blockIdx.x * 64;
    const int rg = w >> 2;                 // rowgroup 0/1
    const int cg = w & 3;                  // 64-col group == expert
    const int rowbase = rg * 32;
    const int nbase = cg * 64;

    // ---- hoisted ldsm addressing (per-thread constants; A-side only) ----
    const uint32_t lr = (uint32_t)(lane & 15);
    const uint32_t lk = (uint32_t)((lane >> 4) << 4);
    const uint32_t csw = (uint32_t)((lane & 7) << 4);
    uint32_t kx[4];
    #pragma unroll
    for (int s = 0; s < 4; ++s) kx[s] = ((uint32_t)(s * 32) + lk) ^ csw;
    const uint32_t aX0 = sb + O_XH + ((uint32_t)rowbase + 0  + lr) * 1024;
    const uint32_t aX1 = sb + O_XH + ((uint32_t)rowbase + 16 + lr) * 1024;
    const uint32_t aV0 = sb + O_V  + ((uint32_t)rowbase + 0  + lr) * 512;
    const uint32_t aV1 = sb + O_V  + ((uint32_t)rowbase + 16 + lr) * 512;

    // per-thread fragment pointer base: + g*2048 (uint4) per pass
    const uint4* __restrict__ wf0 = (const uint4*)gWF + (uint32_t)(cg * 512 + lane);

    float* sG  = (float*)(sm + O_G);
    float* sGS = (float*)(sm + O_GS);

    // ---- init: x -> XH (smem) + XM (global scratch); gate plane staged once ----
    copy16(sm + O_GT, (const char*)gGB, 8192, tid);
    for (int i = tid; i < 64 * 256; i += THREADS) {
        int r = i >> 8, kp = i & 255;
        float2 v = *(const float2*)(x + (size_t)(row0 + r) * 512 + 2 * kp);
        uint32_t hw, mw;
        split2h(v.x, v.y, hw, mw);
        uint32_t off = (uint32_t)r * 1024 + (((uint32_t)(4 * kp)) ^ (((uint32_t)r & 7) << 4));
        *(uint32_t*)(sm + O_XH + off) = hw;
        gXM[(size_t)(row0 + r) * 256 + kp] = mw;
    }
    __syncthreads();

    float acc[2][4][2][4];

    #pragma unroll 1
    for (int L = 0; L < CROSS; ++L) {
        const int g0 = L * 17;
        const uint4* __restrict__ wL = wf0 + (uint32_t)g0 * 2048;

        // ---- gate (warps 0-3, 16 rows each): reads XH + static gate plane ----
        if (w < 4) {
            float ga[4] = {0.f, 0.f, 0.f, 0.f};
            #pragma unroll 4
            for (int s = 0; s < 32; ++s) {
                uint32_t kb = s * 32;
                uint32_t r = (uint32_t)(w * 16) + lr;
                uint32_t ah[4];
                ldsm4(ah, sb + O_XH + r * 1024 + ((kb + lk) ^ ((r & 7) << 4)));
                uint32_t bn = lane & 7;
                uint32_t bk = kb + (((lane >> 3) & 1) << 4);
                uint32_t bh[2];
                ldsm2(bh, sb + O_GT + bn * 1024 + (bk ^ ((bn & 7) << 4)));
                mma_f16(ga, ah, bh[0], bh[1]);
            }
            int c0 = (lane & 3) * 2;
            if (c0 < 4) {
                int r1 = w * 16 + (lane >> 2);
                sG[r1 * 4 + c0] = ga[0];       sG[r1 * 4 + c0 + 1] = ga[1];
                sG[(r1 + 8) * 4 + c0] = ga[2]; sG[(r1 + 8) * 4 + c0 + 1] = ga[3];
            }
        }

        // ---- V: v = tanh(Vs @ x_l), K=512, 8 barrier-free passes ----
        ZEROACC;
        #pragma unroll
        for (int c = 0; c < 8; ++c)
            mma_ldg(aX0 + c * 128, aX1 + c * 128, wL + c * 2048, kx, acc);
        // V epilogue -> V plane
        #pragma unroll
        for (int rf = 0; rf < 2; ++rf)
        #pragma unroll
        for (int t = 0; t < 4; ++t)
        #pragma unroll
        for (int nb = 0; nb < 2; ++nb) {
            float* d = acc[rf][t][nb];
            int n = nbase + t * 16 + nb * 8 + (lane & 3) * 2;
            #pragma unroll
            for (int rr = 0; rr < 2; ++rr) {
                int r = rowbase + rf * 16 + (lane >> 2) + rr * 8;
                uint32_t off = (uint32_t)r * 512 + (((uint32_t)(2 * n)) ^ (((uint32_t)r & 7) << 4));
                *(uint32_t*)(sm + O_V + off) =
                    packh(fast_tanh(d[rr * 2 + 0]), fast_tanh(d[rr * 2 + 1]));
            }
        }
        __syncthreads();   // V plane + sG visible to all

        if (tid < 64)
            sGS[tid] = sG[tid * 4] + sG[tid * 4 + 1] + sG[tid * 4 + 2] + sG[tid * 4 + 3];

        // ---- C: block diagonal, one pass ----
        // warp cg's columns (cg*64..cg*64+63) all belong to expert cg:
        // A k-window = expert's 64 v-columns = byte offset cg*128.
        ZEROACC;
        mma_ldg(aV0 + (uint32_t)cg * 128, aV1 + (uint32_t)cg * 128,
                wL + 8 * 2048, kx, acc);
        __syncthreads();   // all C-mma reads of V done before overwrite
        #pragma unroll
        for (int rf = 0; rf < 2; ++rf)
        #pragma unroll
        for (int t = 0; t < 4; ++t)
        #pragma unroll
        for (int nb = 0; nb < 2; ++nb) {
            float* d = acc[rf][t][nb];
            int n = nbase + t * 16 + nb * 8 + (lane & 3) * 2;
            #pragma unroll
            for (int rr = 0; rr < 2; ++rr) {
                int r = rowbase + rf * 16 + (lane >> 2) + rr * 8;
                float g = sG[r * 4 + cg];
                uint32_t off = (uint32_t)r * 512 + (((uint32_t)(2 * n)) ^ (((uint32_t)r & 7) << 4));
                *(uint32_t*)(sm + O_V + off) =
                    packh(g * fast_tanh(d[rr * 2 + 0]), g * fast_tanh(d[rr * 2 + 1]));
            }
        }
        __syncthreads();   // c' visible

        // ---- U: two 256-d halves x 4 expert chunks; fused combine ----
        #pragma unroll 1
        for (int h = 0; h < 2; ++h) {
            ZEROACC;
            #pragma unroll
            for (int c = 0; c < 4; ++c)
                mma_ldg(aV0 + c * 128, aV1 + c * 128,
                        wL + (9 + h * 4 + c) * 2048, kx, acc);
            // epilogue: out = x0*(u + bias*gs) + x_l
            #pragma unroll
            for (int rf = 0; rf < 2; ++rf)
            #pragma unroll
            for (int t = 0; t < 4; ++t)
            #pragma unroll
            for (int nb = 0; nb < 2; ++nb) {
                float* d = acc[rf][t][nb];
                int dc = h * 256 + nbase + t * 16 + nb * 8 + (lane & 3) * 2;
                float2 bv = *(const float2*)(bias + L * 512 + dc);
                #pragma unroll
                for (int rr = 0; rr < 2; ++rr) {
                    int r = rowbase + rf * 16 + (lane >> 2) + rr * 8;
                    float gs = sGS[r];
                    float2 x0 = *(const float2*)(x + (size_t)(row0 + r) * 512 + dc);
                    uint32_t off = (uint32_t)r * 1024 + (((uint32_t)(2 * dc)) ^ (((uint32_t)r & 7) << 4));
                    size_t xi = (size_t)(row0 + r) * 256 + (dc >> 1);
                    uint32_t xh = *(uint32_t*)(sm + O_XH + off);
                    uint32_t xm = gXM[xi];
                    float xl0 = hlo(xh) + hlo(xm);
                    float xl1 = hhi(xh) + hhi(xm);
                    float o0 = x0.x * (d[rr * 2 + 0] + bv.x * gs) + xl0;
                    float o1 = x0.y * (d[rr * 2 + 1] + bv.y * gs) + xl1;
                    if (L == CROSS - 1) {
                        *(float2*)(out + (size_t)(row0 + r) * 512 + dc) = make_float2(o0, o1);
                    } else {
                        uint32_t hw, mw;
                        split2h(o0, o1, hw, mw);
                        *(uint32_t*)(sm + O_XH + off) = hw;
                        gXM[xi] = mw;
                    }
                }
            }
        }
        __syncthreads();   // XH updated before next layer's reads
    }
}

extern "C" void kernel_launch(void* const* d_in, const int* in_sizes, int n_in,
                              void* d_out, int out_size) {
    const float* x    = (const float*)d_in[0];
    const float* Vs   = (const float*)d_in[1];
    const float* Cs   = (const float*)d_in[2];
    const float* Us   = (const float*)d_in[3];
    const float* bias = (const float*)d_in[4];
    const float* gate = (const float*)d_in[5];
    float* out = (float*)d_out;

    const int total = NPASS * 8192 + 4096;
    prep_kernel<<<(total + 255) / 256, 256>>>(Vs, Cs, Us, gate);

    int rows = in_sizes[0] / 512;
    int grid = rows / 64;

    cudaFuncSetAttribute(dcn_kernel, cudaFuncAttributeMaxDynamicSharedMemorySize, SMEM_BYTES);
    dcn_kernel<<<grid, THREADS, SMEM_BYTES>>>(x, bias, out);
}

// round 16
// speedup vs baseline: 1.1304x; 1.0092x over previous
#include <cuda_runtime.h>
#include <cuda_fp16.h>
#include <stdint.h>

#define CROSS   3
#define THREADS 256
#define NPASS   (CROSS * 17)

// ---------------- fragment-layout weight blob (64-col groups) ----------------
// u32 index: ((((g*4 + cg)*16 + s*4 + t)*32) + lane)*4 + q
// value: halves W_g[n][k], W_g[n][k+1] with
//   n = cg*64 + t*16 + (q&1)*8 + (lane>>2)
//   k = s*16 + (q>>1)*8 + 2*(lane&3)
__device__ __align__(16) uint32_t gWF[NPASS * 8192];
// gate plane image: [8 n][512 k] fp16, rowstride 1024B
__device__ __align__(16) __half gGB[4096];
// x_l mid plane scratch: one u32 (half2) per (row, dc-pair): [32768][256]
__device__ __align__(16) uint32_t gXM[32768u * 256u];

__global__ void prep_kernel(const float* __restrict__ Vs,
                            const float* __restrict__ Cs,
                            const float* __restrict__ Us,
                            const float* __restrict__ gw) {
    int idx = blockIdx.x * 256 + threadIdx.x;
    const int NF = NPASS * 8192;
    if (idx < NF) {
        int q    = idx & 3;
        int lane = (idx >> 2) & 31;
        int t    = (idx >> 7) & 3;
        int s    = (idx >> 9) & 3;
        int cg   = (idx >> 11) & 3;
        int g    = idx >> 13;
        int n = cg * 64 + t * 16 + (q & 1) * 8 + (lane >> 2);
        int k = s * 16 + ((q >> 1) & 1) * 8 + 2 * (lane & 3);
        int L = g / 17, p = g - L * 17;
        float w0, w1;
        if (p < 8) {
            const float* src = Vs + (size_t)(L * 256 + n) * 512 + p * 64 + k;
            w0 = src[0]; w1 = src[1];
        } else if (p == 8) {
            const float* src = Cs + (size_t)L * 16384 + n * 64 + k;
            w0 = src[0]; w1 = src[1];
        } else {
            int qq = p - 9, h = qq >> 2, c = qq & 3;
            const float* src = Us + ((size_t)(L * 4 + c) * 512 + h * 256 + n) * 64 + k;
            w0 = src[0]; w1 = src[1];
        }
        __half h0 = __float2half_rn(w0), h1 = __float2half_rn(w1);
        gWF[idx] = (uint32_t)*(unsigned short*)&h0 | ((uint32_t)*(unsigned short*)&h1 << 16);
        return;
    }
    idx -= NF;
    if (idx < 4096) {
        int n = idx >> 9, k = idx & 511;
        float w = (n < 4) ? gw[k * 4 + n] : 0.f;
        gGB[(n * 1024 + ((2 * k) ^ ((n & 7) << 4))) >> 1] = __float2half_rn(w);
    }
}

// ---------------- warp-level primitives ----------------
__device__ __forceinline__ uint32_t s2u(const void* p) {
    uint32_t a;
    asm("{ .reg .u64 t; cvta.to.shared.u64 t, %1; cvt.u32.u64 %0, t; }" : "=r"(a) : "l"(p));
    return a;
}
__device__ __forceinline__ void ldsm4(uint32_t r[4], uint32_t addr) {
    asm volatile("ldmatrix.sync.aligned.m8n8.x4.shared.b16 {%0,%1,%2,%3}, [%4];"
                 : "=r"(r[0]), "=r"(r[1]), "=r"(r[2]), "=r"(r[3]) : "r"(addr));
}
__device__ __forceinline__ void ldsm2(uint32_t r[2], uint32_t addr) {
    asm volatile("ldmatrix.sync.aligned.m8n8.x2.shared.b16 {%0,%1}, [%2];"
                 : "=r"(r[0]), "=r"(r[1]) : "r"(addr));
}
__device__ __forceinline__ void mma_f16(float d[4], const uint32_t a[4], const uint32_t b0, const uint32_t b1) {
    asm volatile("mma.sync.aligned.m16n8k16.row.col.f32.f16.f16.f32 "
                 "{%0,%1,%2,%3}, {%4,%5,%6,%7}, {%8,%9}, {%0,%1,%2,%3};"
                 : "+f"(d[0]), "+f"(d[1]), "+f"(d[2]), "+f"(d[3])
                 : "r"(a[0]), "r"(a[1]), "r"(a[2]), "r"(a[3]), "r"(b0), "r"(b1));
}
__device__ __forceinline__ float fast_tanh(float x) {
    asm("tanh.approx.f32 %0, %0;" : "+f"(x));
    return x;
}
__device__ __forceinline__ uint32_t packh(float a, float b) {
    __half2 p = __floats2half2_rn(a, b);
    return *(uint32_t*)&p;
}
__device__ __forceinline__ void split2h(float a, float b, uint32_t& hw, uint32_t& mw) {
    __half h0 = __float2half_rn(a), h1 = __float2half_rn(b);
    __half m0 = __float2half_rn(a - __half2float(h0));
    __half m1 = __float2half_rn(b - __half2float(h1));
    hw = (uint32_t)*(unsigned short*)&h0 | ((uint32_t)*(unsigned short*)&h1 << 16);
    mw = (uint32_t)*(unsigned short*)&m0 | ((uint32_t)*(unsigned short*)&m1 << 16);
}
__device__ __forceinline__ float hlo(uint32_t w) {
    unsigned short s = (unsigned short)(w & 0xFFFF);
    return __half2float(*(__half*)&s);
}
__device__ __forceinline__ float hhi(uint32_t w) {
    unsigned short s = (unsigned short)(w >> 16);
    return __half2float(*(__half*)&s);
}
__device__ __forceinline__ void copy16(char* dst, const char* src, int bytes, int tid) {
    const float4* s = (const float4*)src;
    float4* d = (float4*)dst;
    for (int i = tid; i < bytes / 16; i += THREADS) d[i] = s[i];
}

// warp tile = 32 rows x 64 cols. acc[rowfrag 2][n16 4][n8 2][4].
// A via ldsm from smem plane; B via direct LDG.128 of fragment blob,
// staged in FOUR rounds of 4 uint4 (one k-step each) to bound register pressure.
__device__ __forceinline__ void mma_ldg(
    uint32_t aB0, uint32_t aB1,
    const uint4* __restrict__ wp,        // gWF_u4 + g*2048 + cg*512 + lane
    const uint32_t kx[4],
    float (&acc)[2][4][2][4])
{
    #pragma unroll
    for (int s = 0; s < 4; ++s) {
        uint4 b[4];
        #pragma unroll
        for (int i = 0; i < 4; ++i) b[i] = __ldg(wp + (s * 4 + i) * 32);
        uint32_t a0[4], a1[4];
        ldsm4(a0, aB0 + kx[s]);
        ldsm4(a1, aB1 + kx[s]);
        #pragma unroll
        for (int t = 0; t < 4; ++t) {
            const uint4 bb = b[t];
            mma_f16(acc[0][t][0], a0, bb.x, bb.z);
            mma_f16(acc[0][t][1], a0, bb.y, bb.w);
            mma_f16(acc[1][t][0], a1, bb.x, bb.z);
            mma_f16(acc[1][t][1], a1, bb.y, bb.w);
        }
    }
}

#define ZEROACC                                       \
    _Pragma("unroll") for (int zi = 0; zi < 2; ++zi)  \
    _Pragma("unroll") for (int zj = 0; zj < 4; ++zj)  \
    _Pragma("unroll") for (int zk = 0; zk < 2; ++zk)  \
    _Pragma("unroll") for (int zl = 0; zl < 4; ++zl) acc[zi][zj][zk][zl] = 0.f;

// smem byte offsets (64-row CTA; XM lives in global scratch)
#define O_XH 0          // x_l hi plane  [64][512] fp16 (64KB)
#define O_V  65536      // v / c' plane  [64][256] fp16 (32KB)
#define O_GT 98304      // gate plane (8KB, staged once)
#define O_G  106496     // sG [64][4] f32 (1KB)
#define O_GS 107520     // sGS [64] f32 (256B)
#define SMEM_BYTES 107776

__global__ void __launch_bounds__(THREADS, 2)
dcn_kernel(const float* __restrict__ x,
           const float* __restrict__ bias,
           float* __restrict__ out)
{
    extern __shared__ char sm[];
    const uint32_t sb = s2u(sm);
    const int tid = threadIdx.x;
    const int w = tid >> 5, lane = tid & 31;
    const int row0 = blockIdx.x * 64;
    const int rg = w >> 2;                 // rowgroup 0/1
    const int cg = w & 3;                  // 64-col group == expert
    const int rowbase = rg * 32;
    const int nbase = cg * 64;

    // ---- hoisted ldsm addressing (per-thread constants; A-side only) ----
    const uint32_t lr = (uint32_t)(lane & 15);
    const uint32_t lk = (uint32_t)((lane >> 4) << 4);
    const uint32_t csw = (uint32_t)((lane & 7) << 4);
    uint32_t kx[4];
    #pragma unroll
    for (int s = 0; s < 4; ++s) kx[s] = ((uint32_t)(s * 32) + lk) ^ csw;
    const uint32_t aX0 = sb + O_XH + ((uint32_t)rowbase + 0  + lr) * 1024;
    const uint32_t aX1 = sb + O_XH + ((uint32_t)rowbase + 16 + lr) * 1024;
    const uint32_t aV0 = sb + O_V  + ((uint32_t)rowbase + 0  + lr) * 512;
    const uint32_t aV1 = sb + O_V  + ((uint32_t)rowbase + 16 + lr) * 512;

    // per-thread fragment pointer base: + g*2048 (uint4) per pass
    const uint4* __restrict__ wf0 = (const uint4*)gWF + (uint32_t)(cg * 512 + lane);

    float* sG  = (float*)(sm + O_G);
    float* sGS = (float*)(sm + O_GS);

    // ---- init: x -> XH (smem) + XM (global scratch); gate plane staged once ----
    copy16(sm + O_GT, (const char*)gGB, 8192, tid);
    for (int i = tid; i < 64 * 256; i += THREADS) {
        int r = i >> 8, kp = i & 255;
        float2 v = *(const float2*)(x + (size_t)(row0 + r) * 512 + 2 * kp);
        uint32_t hw, mw;
        split2h(v.x, v.y, hw, mw);
        uint32_t off = (uint32_t)r * 1024 + (((uint32_t)(4 * kp)) ^ (((uint32_t)r & 7) << 4));
        *(uint32_t*)(sm + O_XH + off) = hw;
        gXM[(size_t)(row0 + r) * 256 + kp] = mw;
    }
    __syncthreads();

    float acc[2][4][2][4];

    #pragma unroll 1
    for (int L = 0; L < CROSS; ++L) {
        const int g0 = L * 17;
        const uint4* __restrict__ wL = wf0 + (uint32_t)g0 * 2048;

        // ---- gate (warps 0-3, 16 rows each): reads XH + static gate plane ----
        if (w < 4) {
            float ga[4] = {0.f, 0.f, 0.f, 0.f};
            #pragma unroll 4
            for (int s = 0; s < 32; ++s) {
                uint32_t kb = s * 32;
                uint32_t r = (uint32_t)(w * 16) + lr;
                uint32_t ah[4];
                ldsm4(ah, sb + O_XH + r * 1024 + ((kb + lk) ^ ((r & 7) << 4)));
                uint32_t bn = lane & 7;
                uint32_t bk = kb + (((lane >> 3) & 1) << 4);
                uint32_t bh[2];
                ldsm2(bh, sb + O_GT + bn * 1024 + (bk ^ ((bn & 7) << 4)));
                mma_f16(ga, ah, bh[0], bh[1]);
            }
            int c0 = (lane & 3) * 2;
            if (c0 < 4) {
                int r1 = w * 16 + (lane >> 2);
                sG[r1 * 4 + c0] = ga[0];       sG[r1 * 4 + c0 + 1] = ga[1];
                sG[(r1 + 8) * 4 + c0] = ga[2]; sG[(r1 + 8) * 4 + c0 + 1] = ga[3];
            }
        }

        // ---- V: v = tanh(Vs @ x_l), K=512, 8 barrier-free passes ----
        ZEROACC;
        #pragma unroll
        for (int c = 0; c < 8; ++c)
            mma_ldg(aX0 + c * 128, aX1 + c * 128, wL + c * 2048, kx, acc);
        // V epilogue -> V plane
        #pragma unroll
        for (int rf = 0; rf < 2; ++rf)
        #pragma unroll
        for (int t = 0; t < 4; ++t)
        #pragma unroll
        for (int nb = 0; nb < 2; ++nb) {
            float* d = acc[rf][t][nb];
            int n = nbase + t * 16 + nb * 8 + (lane & 3) * 2;
            #pragma unroll
            for (int rr = 0; rr < 2; ++rr) {
                int r = rowbase + rf * 16 + (lane >> 2) + rr * 8;
                uint32_t off = (uint32_t)r * 512 + (((uint32_t)(2 * n)) ^ (((uint32_t)r & 7) << 4));
                *(uint32_t*)(sm + O_V + off) =
                    packh(fast_tanh(d[rr * 2 + 0]), fast_tanh(d[rr * 2 + 1]));
            }
        }
        __syncthreads();   // V plane + sG visible to all

        if (tid < 64)
            sGS[tid] = sG[tid * 4] + sG[tid * 4 + 1] + sG[tid * 4 + 2] + sG[tid * 4 + 3];

        // ---- C: block diagonal, one pass ----
        // warp cg's columns (cg*64..cg*64+63) all belong to expert cg:
        // A k-window = expert's 64 v-columns = byte offset cg*128.
        ZEROACC;
        mma_ldg(aV0 + (uint32_t)cg * 128, aV1 + (uint32_t)cg * 128,
                wL + 8 * 2048, kx, acc);
        __syncthreads();   // all C-mma reads of V done before overwrite
        #pragma unroll
        for (int rf = 0; rf < 2; ++rf)
        #pragma unroll
        for (int t = 0; t < 4; ++t)
        #pragma unroll
        for (int nb = 0; nb < 2; ++nb) {
            float* d = acc[rf][t][nb];
            int n = nbase + t * 16 + nb * 8 + (lane & 3) * 2;
            #pragma unroll
            for (int rr = 0; rr < 2; ++rr) {
                int r = rowbase + rf * 16 + (lane >> 2) + rr * 8;
                float g = sG[r * 4 + cg];
                uint32_t off = (uint32_t)r * 512 + (((uint32_t)(2 * n)) ^ (((uint32_t)r & 7) << 4));
                *(uint32_t*)(sm + O_V + off) =
                    packh(g * fast_tanh(d[rr * 2 + 0]), g * fast_tanh(d[rr * 2 + 1]));
            }
        }
        __syncthreads();   // c' visible

        // ---- U: two 256-d halves x 4 expert chunks; fused combine ----
        #pragma unroll 1
        for (int h = 0; h < 2; ++h) {
            ZEROACC;
            #pragma unroll
            for (int c = 0; c < 4; ++c)
                mma_ldg(aV0 + c * 128, aV1 + c * 128,
                        wL + (9 + h * 4 + c) * 2048, kx, acc);
            // epilogue: out = x0*(u + bias*gs) + x_l
            #pragma unroll
            for (int rf = 0; rf < 2; ++rf)
            #pragma unroll
            for (int t = 0; t < 4; ++t)
            #pragma unroll
            for (int nb = 0; nb < 2; ++nb) {
                float* d = acc[rf][t][nb];
                int dc = h * 256 + nbase + t * 16 + nb * 8 + (lane & 3) * 2;
                float2 bv = *(const float2*)(bias + L * 512 + dc);
                #pragma unroll
                for (int rr = 0; rr < 2; ++rr) {
                    int r = rowbase + rf * 16 + (lane >> 2) + rr * 8;
                    float gs = sGS[r];
                    float2 x0 = *(const float2*)(x + (size_t)(row0 + r) * 512 + dc);
                    uint32_t off = (uint32_t)r * 1024 + (((uint32_t)(2 * dc)) ^ (((uint32_t)r & 7) << 4));
                    size_t xi = (size_t)(row0 + r) * 256 + (dc >> 1);
                    uint32_t xh = *(uint32_t*)(sm + O_XH + off);
                    uint32_t xm = gXM[xi];
                    float xl0 = hlo(xh) + hlo(xm);
                    float xl1 = hhi(xh) + hhi(xm);
                    float o0 = x0.x * (d[rr * 2 + 0] + bv.x * gs) + xl0;
                    float o1 = x0.y * (d[rr * 2 + 1] + bv.y * gs) + xl1;
                    if (L == CROSS - 1) {
                        *(float2*)(out + (size_t)(row0 + r) * 512 + dc) = make_float2(o0, o1);
                    } else {
                        uint32_t hw, mw;
                        split2h(o0, o1, hw, mw);
                        *(uint32_t*)(sm + O_XH + off) = hw;
                        gXM[xi] = mw;
                    }
                }
            }
        }
        __syncthreads();   // XH updated before next layer's reads
    }
}

extern "C" void kernel_launch(void* const* d_in, const int* in_sizes, int n_in,
                              void* d_out, int out_size) {
    const float* x    = (const float*)d_in[0];
    const float* Vs   = (const float*)d_in[1];
    const float* Cs   = (const float*)d_in[2];
    const float* Us   = (const float*)d_in[3];
    const float* bias = (const float*)d_in[4];
    const float* gate = (const float*)d_in[5];
    float* out = (float*)d_out;

    const int total = NPASS * 8192 + 4096;
    prep_kernel<<<(total + 255) / 256, 256>>>(Vs, Cs, Us, gate);

    int rows = in_sizes[0] / 512;
    int grid = rows / 64;

    cudaFuncSetAttribute(dcn_kernel, cudaFuncAttributeMaxDynamicSharedMemorySize, SMEM_BYTES);
    dcn_kernel<<<grid, THREADS, SMEM_BYTES>>>(x, bias, out);
}

// round 17
// speedup vs baseline: 1.2985x; 1.1487x over previous
#include <cuda_runtime.h>
#include <cuda_fp16.h>
#include <stdint.h>

#define CROSS   3
#define THREADS 256
#define NPASS   (CROSS * 17)

// ---------------- fragment-layout weight blob (32-col groups) ----------------
// u32 index: (((g*8 + cg)*8 + (s*2+t))*32 + lane)*4 + q
// value: halves W_g[n][k], W_g[n][k+1] with
//   n = cg*32 + t*16 + (q&1)*8 + (lane>>2)
//   k = s*16 + (q>>1)*8 + 2*(lane&3)
__device__ __align__(16) uint32_t gWF[NPASS * 8192];
// gate plane image: [8 n][512 k] fp16, rowstride 1024B
__device__ __align__(16) __half gGB[4096];
// x_l mid plane scratch: one u32 (half2) per (row, dc-pair): [32768][256]
__device__ __align__(16) uint32_t gXM[32768u * 256u];

__global__ void prep_kernel(const float* __restrict__ Vs,
                            const float* __restrict__ Cs,
                            const float* __restrict__ Us,
                            const float* __restrict__ gw) {
    int idx = blockIdx.x * 256 + threadIdx.x;
    const int NF = NPASS * 8192;
    if (idx < NF) {
        int u = idx;
        int q    = u & 3;  u >>= 2;
        int lane = u & 31; u >>= 5;
        int st   = u & 7;  u >>= 3;
        int cg   = u & 7;  u >>= 3;
        int g    = u;
        int s = st >> 1, t = st & 1;
        int n = cg * 32 + t * 16 + (q & 1) * 8 + (lane >> 2);
        int k = s * 16 + ((q >> 1) & 1) * 8 + 2 * (lane & 3);
        int L = g / 17, p = g - L * 17;
        float w0, w1;
        if (p < 8) {
            const float* src = Vs + (size_t)(L * 256 + n) * 512 + p * 64 + k;
            w0 = src[0]; w1 = src[1];
        } else if (p == 8) {
            const float* src = Cs + (size_t)L * 16384 + n * 64 + k;
            w0 = src[0]; w1 = src[1];
        } else {
            int qq = p - 9, h = qq >> 2, c = qq & 3;
            const float* src = Us + ((size_t)(L * 4 + c) * 512 + h * 256 + n) * 64 + k;
            w0 = src[0]; w1 = src[1];
        }
        __half h0 = __float2half_rn(w0), h1 = __float2half_rn(w1);
        gWF[idx] = (uint32_t)*(unsigned short*)&h0 | ((uint32_t)*(unsigned short*)&h1 << 16);
        return;
    }
    idx -= NF;
    if (idx < 4096) {
        int n = idx >> 9, k = idx & 511;
        float w = (n < 4) ? gw[k * 4 + n] : 0.f;
        gGB[(n * 1024 + ((2 * k) ^ ((n & 7) << 4))) >> 1] = __float2half_rn(w);
    }
}

// ---------------- warp-level primitives ----------------
__device__ __forceinline__ uint32_t s2u(const void* p) {
    uint32_t a;
    asm("{ .reg .u64 t; cvta.to.shared.u64 t, %1; cvt.u32.u64 %0, t; }" : "=r"(a) : "l"(p));
    return a;
}
__device__ __forceinline__ void ldsm4(uint32_t r[4], uint32_t addr) {
    asm volatile("ldmatrix.sync.aligned.m8n8.x4.shared.b16 {%0,%1,%2,%3}, [%4];"
                 : "=r"(r[0]), "=r"(r[1]), "=r"(r[2]), "=r"(r[3]) : "r"(addr));
}
__device__ __forceinline__ void ldsm2(uint32_t r[2], uint32_t addr) {
    asm volatile("ldmatrix.sync.aligned.m8n8.x2.shared.b16 {%0,%1}, [%2];"
                 : "=r"(r[0]), "=r"(r[1]) : "r"(addr));
}
__device__ __forceinline__ void mma_f16(float d[4], const uint32_t a[4], const uint32_t b0, const uint32_t b1) {
    asm volatile("mma.sync.aligned.m16n8k16.row.col.f32.f16.f16.f32 "
                 "{%0,%1,%2,%3}, {%4,%5,%6,%7}, {%8,%9}, {%0,%1,%2,%3};"
                 : "+f"(d[0]), "+f"(d[1]), "+f"(d[2]), "+f"(d[3])
                 : "r"(a[0]), "r"(a[1]), "r"(a[2]), "r"(a[3]), "r"(b0), "r"(b1));
}
__device__ __forceinline__ float fast_tanh(float x) {
    asm("tanh.approx.f32 %0, %0;" : "+f"(x));
    return x;
}
__device__ __forceinline__ uint32_t packh(float a, float b) {
    __half2 p = __floats2half2_rn(a, b);
    return *(uint32_t*)&p;
}
__device__ __forceinline__ void split2h(float a, float b, uint32_t& hw, uint32_t& mw) {
    __half h0 = __float2half_rn(a), h1 = __float2half_rn(b);
    __half m0 = __float2half_rn(a - __half2float(h0));
    __half m1 = __float2half_rn(b - __half2float(h1));
    hw = (uint32_t)*(unsigned short*)&h0 | ((uint32_t)*(unsigned short*)&h1 << 16);
    mw = (uint32_t)*(unsigned short*)&m0 | ((uint32_t)*(unsigned short*)&m1 << 16);
}
__device__ __forceinline__ float hlo(uint32_t w) {
    unsigned short s = (unsigned short)(w & 0xFFFF);
    return __half2float(*(__half*)&s);
}
__device__ __forceinline__ float hhi(uint32_t w) {
    unsigned short s = (unsigned short)(w >> 16);
    return __half2float(*(__half*)&s);
}
__device__ __forceinline__ void copy16(char* dst, const char* src, int bytes, int tid) {
    const float4* s = (const float4*)src;
    float4* d = (float4*)dst;
    for (int i = tid; i < bytes / 16; i += THREADS) d[i] = s[i];
}

// warp tile = 32 rows x 32 cols. acc[rowfrag 2][n16 2][n8 2][4].
// A via ldsm from smem plane; B via direct LDG.128 of fragment blob.
__device__ __forceinline__ void mma_ldg(
    uint32_t aB0, uint32_t aB1,
    const uint4* __restrict__ wp,        // gWF_u4 + g*2048 + cg*256 + lane
    const uint32_t kx[4],
    float (&acc)[2][2][2][4])
{
    uint4 b[8];
    #pragma unroll
    for (int i = 0; i < 8; ++i) b[i] = __ldg(wp + i * 32);
    #pragma unroll
    for (int s = 0; s < 4; ++s) {
        uint32_t a0[4], a1[4];
        ldsm4(a0, aB0 + kx[s]);
        ldsm4(a1, aB1 + kx[s]);
        const uint4 b0 = b[s * 2 + 0];
        const uint4 b1 = b[s * 2 + 1];
        mma_f16(acc[0][0][0], a0, b0.x, b0.z);
        mma_f16(acc[0][0][1], a0, b0.y, b0.w);
        mma_f16(acc[0][1][0], a0, b1.x, b1.z);
        mma_f16(acc[0][1][1], a0, b1.y, b1.w);
        mma_f16(acc[1][0][0], a1, b0.x, b0.z);
        mma_f16(acc[1][0][1], a1, b0.y, b0.w);
        mma_f16(acc[1][1][0], a1, b1.x, b1.z);
        mma_f16(acc[1][1][1], a1, b1.y, b1.w);
    }
}

#define ZEROACC                                       \
    _Pragma("unroll") for (int zi = 0; zi < 2; ++zi)  \
    _Pragma("unroll") for (int zj = 0; zj < 2; ++zj)  \
    _Pragma("unroll") for (int zk = 0; zk < 2; ++zk)  \
    _Pragma("unroll") for (int zl = 0; zl < 4; ++zl) acc[zi][zj][zk][zl] = 0.f;

// smem byte offsets (32-row CTA; XM lives in global scratch)
#define O_XH 0          // x_l hi plane  [32][512] fp16 (32KB)
#define O_V  32768      // v / c' plane  [32][256] fp16 (16KB)
#define O_GT 49152      // gate plane (8KB, staged once)
#define O_G  57344      // sG [32][4] f32 (512B)
#define O_GS 57856      // sGS [32] f32 (128B)
#define SMEM_BYTES 58112

__global__ void __launch_bounds__(THREADS, 2)
dcn_kernel(const float* __restrict__ x,
           const float* __restrict__ bias,
           float* __restrict__ out)
{
    extern __shared__ char sm[];
    const uint32_t sb = s2u(sm);
    const int tid = threadIdx.x;
    const int w = tid >> 5, lane = tid & 31;
    const int row0 = blockIdx.x * 32;
    const int cg = w;                      // 0..7 (32-col groups)
    const int nbase = cg * 32;
    const int ec = cg >> 1;                // expert for C phase

    // ---- hoisted ldsm addressing (per-thread constants; A-side only) ----
    const uint32_t lr = (uint32_t)(lane & 15);
    const uint32_t lk = (uint32_t)((lane >> 4) << 4);
    const uint32_t csw = (uint32_t)((lane & 7) << 4);
    uint32_t kx[4];
    #pragma unroll
    for (int s = 0; s < 4; ++s) kx[s] = ((uint32_t)(s * 32) + lk) ^ csw;
    const uint32_t aX0 = sb + O_XH + (0  + lr) * 1024;
    const uint32_t aX1 = sb + O_XH + (16 + lr) * 1024;
    const uint32_t aV0 = sb + O_V  + (0  + lr) * 512;
    const uint32_t aV1 = sb + O_V  + (16 + lr) * 512;

    // per-thread fragment pointer base: + g*2048 (uint4) per pass
    const uint4* __restrict__ wf0 = (const uint4*)gWF + (uint32_t)(cg * 256 + lane);

    float* sG  = (float*)(sm + O_G);
    float* sGS = (float*)(sm + O_GS);

    // ---- init: x -> XH (smem) + XM (global scratch); gate plane staged once ----
    copy16(sm + O_GT, (const char*)gGB, 8192, tid);
    for (int i = tid; i < 32 * 256; i += THREADS) {
        int r = i >> 8, kp = i & 255;
        float2 v = *(const float2*)(x + (size_t)(row0 + r) * 512 + 2 * kp);
        uint32_t hw, mw;
        split2h(v.x, v.y, hw, mw);
        uint32_t off = (uint32_t)r * 1024 + (((uint32_t)(4 * kp)) ^ (((uint32_t)r & 7) << 4));
        *(uint32_t*)(sm + O_XH + off) = hw;
        gXM[(size_t)(row0 + r) * 256 + kp] = mw;
    }
    __syncthreads();

    float acc[2][2][2][4];

    #pragma unroll 1
    for (int L = 0; L < CROSS; ++L) {
        const int g0 = L * 17;
        const uint4* __restrict__ wL = wf0 + (uint32_t)g0 * 2048;

        // ---- gate (warps 0-1): reads XH + static gate plane ----
        if (w < 2) {
            float ga[4] = {0.f, 0.f, 0.f, 0.f};
            #pragma unroll 4
            for (int s = 0; s < 32; ++s) {
                uint32_t kb = s * 32;
                uint32_t r = (uint32_t)(w * 16) + lr;
                uint32_t ah[4];
                ldsm4(ah, sb + O_XH + r * 1024 + ((kb + lk) ^ ((r & 7) << 4)));
                uint32_t bn = lane & 7;
                uint32_t bk = kb + (((lane >> 3) & 1) << 4);
                uint32_t bh[2];
                ldsm2(bh, sb + O_GT + bn * 1024 + (bk ^ ((bn & 7) << 4)));
                mma_f16(ga, ah, bh[0], bh[1]);
            }
            int c0 = (lane & 3) * 2;
            if (c0 < 4) {
                int r1 = w * 16 + (lane >> 2);
                sG[r1 * 4 + c0] = ga[0];       sG[r1 * 4 + c0 + 1] = ga[1];
                sG[(r1 + 8) * 4 + c0] = ga[2]; sG[(r1 + 8) * 4 + c0 + 1] = ga[3];
            }
        }

        // ---- V: v = tanh(Vs @ x_l), K=512, 8 barrier-free passes ----
        ZEROACC;
        #pragma unroll
        for (int c = 0; c < 8; ++c)
            mma_ldg(aX0 + c * 128, aX1 + c * 128, wL + c * 2048, kx, acc);
        // V epilogue -> V plane
        #pragma unroll
        for (int rf = 0; rf < 2; ++rf)
        #pragma unroll
        for (int t = 0; t < 2; ++t)
        #pragma unroll
        for (int nb = 0; nb < 2; ++nb) {
            float* d = acc[rf][t][nb];
            int n = nbase + t * 16 + nb * 8 + (lane & 3) * 2;
            #pragma unroll
            for (int rr = 0; rr < 2; ++rr) {
                int r = rf * 16 + (lane >> 2) + rr * 8;
                uint32_t off = (uint32_t)r * 512 + (((uint32_t)(2 * n)) ^ (((uint32_t)r & 7) << 4));
                *(uint32_t*)(sm + O_V + off) =
                    packh(fast_tanh(d[rr * 2 + 0]), fast_tanh(d[rr * 2 + 1]));
            }
        }
        __syncthreads();   // V plane + sG visible to all

        if (tid < 32)
            sGS[tid] = sG[tid * 4] + sG[tid * 4 + 1] + sG[tid * 4 + 2] + sG[tid * 4 + 3];

        // ---- C: block diagonal, one pass ----
        ZEROACC;
        mma_ldg(aV0 + (uint32_t)ec * 128, aV1 + (uint32_t)ec * 128,
                wL + 8 * 2048, kx, acc);
        __syncthreads();   // all C-mma reads of V done before overwrite
        #pragma unroll
        for (int rf = 0; rf < 2; ++rf)
        #pragma unroll
        for (int t = 0; t < 2; ++t)
        #pragma unroll
        for (int nb = 0; nb < 2; ++nb) {
            float* d = acc[rf][t][nb];
            int n = nbase + t * 16 + nb * 8 + (lane & 3) * 2;
            #pragma unroll
            for (int rr = 0; rr < 2; ++rr) {
                int r = rf * 16 + (lane >> 2) + rr * 8;
                float g = sG[r * 4 + ec];
                uint32_t off = (uint32_t)r * 512 + (((uint32_t)(2 * n)) ^ (((uint32_t)r & 7) << 4));
                *(uint32_t*)(sm + O_V + off) =
                    packh(g * fast_tanh(d[rr * 2 + 0]), g * fast_tanh(d[rr * 2 + 1]));
            }
        }
        __syncthreads();   // c' visible

        // ---- U: two 256-d halves x 4 expert chunks; fused combine ----
        #pragma unroll 1
        for (int h = 0; h < 2; ++h) {
            ZEROACC;
            #pragma unroll
            for (int c = 0; c < 4; ++c)
                mma_ldg(aV0 + c * 128, aV1 + c * 128,
                        wL + (9 + h * 4 + c) * 2048, kx, acc);
            // epilogue: out = x0*(u + bias*gs) + x_l
            #pragma unroll
            for (int rf = 0; rf < 2; ++rf)
            #pragma unroll
            for (int t = 0; t < 2; ++t)
            #pragma unroll
            for (int nb = 0; nb < 2; ++nb) {
                float* d = acc[rf][t][nb];
                int dc = h * 256 + nbase + t * 16 + nb * 8 + (lane & 3) * 2;
                float2 bv = *(const float2*)(bias + L * 512 + dc);
                #pragma unroll
                for (int rr = 0; rr < 2; ++rr) {
                    int r = rf * 16 + (lane >> 2) + rr * 8;
                    float gs = sGS[r];
                    float2 x0 = *(const float2*)(x + (size_t)(row0 + r) * 512 + dc);
                    uint32_t off = (uint32_t)r * 1024 + (((uint32_t)(2 * dc)) ^ (((uint32_t)r & 7) << 4));
                    size_t xi = (size_t)(row0 + r) * 256 + (dc >> 1);
                    uint32_t xh = *(uint32_t*)(sm + O_XH + off);
                    uint32_t xm = gXM[xi];
                    float xl0 = hlo(xh) + hlo(xm);
                    float xl1 = hhi(xh) + hhi(xm);
                    float o0 = x0.x * (d[rr * 2 + 0] + bv.x * gs) + xl0;
                    float o1 = x0.y * (d[rr * 2 + 1] + bv.y * gs) + xl1;
                    if (L == CROSS - 1) {
                        *(float2*)(out + (size_t)(row0 + r) * 512 + dc) = make_float2(o0, o1);
                    } else {
                        uint32_t hw, mw;
                        split2h(o0, o1, hw, mw);
                        *(uint32_t*)(sm + O_XH + off) = hw;
                        gXM[xi] = mw;
                    }
                }
            }
        }
        __syncthreads();   // XH updated before next layer's reads
    }
}

extern "C" void kernel_launch(void* const* d_in, const int* in_sizes, int n_in,
                              void* d_out, int out_size) {
    const float* x    = (const float*)d_in[0];
    const float* Vs   = (const float*)d_in[1];
    const float* Cs   = (const float*)d_in[2];
    const float* Us   = (const float*)d_in[3];
    const float* bias = (const float*)d_in[4];
    const float* gate = (const float*)d_in[5];
    float* out = (float*)d_out;

    const int total = NPASS * 8192 + 4096;
    prep_kernel<<<(total + 255) / 256, 256>>>(Vs, Cs, Us, gate);

    int rows = in_sizes[0] / 512;
    int grid = rows / 32;

    cudaFuncSetAttribute(dcn_kernel, cudaFuncAttributeMaxDynamicSharedMemorySize, SMEM_BYTES);
    // keep smem carveout minimal so the rest of the 228KB unified cache serves
    // the B-fragment LDG stream as L1D
    cudaFuncSetAttribute(dcn_kernel, cudaFuncAttributePreferredSharedMemoryCarveout, 50);
    dcn_kernel<<<grid, THREADS, SMEM_BYTES>>>(x, bias, out);
}